// round 10
// baseline (speedup 1.0000x reference)
#include <cuda_runtime.h>
#include <cuda_bf16.h>
#include <cstdint>
#include <math.h>

#define T_ 512
#define B_ 64
#define H_ 512
#define KK_ 16
#define M_ (T_*B_)       // 32768
#define NCHK 31          // 16-step chunk matrices per batch
#define NP2  15          // 32-step (paired) matrices per batch

// ---------------- device scratch (allocation-free rule) ----------------
__device__ __nv_bfloat16 g_Xb[M_ * H_];    // 32 MB  X in bf16
__device__ __nv_bfloat16 g_W1T[H_ * H_];   // 0.5 MB W1^T in bf16
__device__ float g_em[M_ * KK_];           // 2 MB emissions (atomic-accumulated)
__device__ float g_P[B_ * NCHK * 16 * 16]; // 16-step matrices, exp-form rows
__device__ float g_R[B_ * NCHK * 16];      // row maxes
__device__ float g_P32[B_ * NP2 * 16 * 16];// 32-step matrices, exp-form rows
__device__ float g_R32[B_ * NP2 * 16];     // row maxes

// ---------------- helpers ----------------
__device__ __forceinline__ uint32_t smem_u32(const void* p) {
    uint32_t a;
    asm("{ .reg .u64 t; cvta.to.shared.u64 t, %1; cvt.u32.u64 %0, t; }"
        : "=r"(a) : "l"(p));
    return a;
}
__device__ __forceinline__ void cp_async16(uint32_t dst, const void* src) {
    asm volatile("cp.async.cg.shared.global [%0], [%1], 16;\n" :: "r"(dst), "l"(src));
}
#define CP_COMMIT() asm volatile("cp.async.commit_group;\n" ::: "memory")
#define CP_WAIT(n)  asm volatile("cp.async.wait_group %0;\n" :: "n"(n) : "memory")

__device__ __forceinline__ void mma16816(float* d, const uint32_t* a, const uint32_t* b) {
    asm volatile(
        "mma.sync.aligned.m16n8k16.row.col.f32.bf16.bf16.f32 "
        "{%0,%1,%2,%3}, {%4,%5,%6,%7}, {%8,%9}, {%0,%1,%2,%3};\n"
        : "+f"(d[0]), "+f"(d[1]), "+f"(d[2]), "+f"(d[3])
        : "r"(a[0]), "r"(a[1]), "r"(a[2]), "r"(a[3]), "r"(b[0]), "r"(b[1]));
}
__device__ __forceinline__ void ldsm_x4(uint32_t* r, uint32_t addr) {
    asm volatile("ldmatrix.sync.aligned.m8n8.x4.shared.b16 {%0,%1,%2,%3}, [%4];\n"
                 : "=r"(r[0]), "=r"(r[1]), "=r"(r[2]), "=r"(r[3]) : "r"(addr));
}
__device__ __forceinline__ uint32_t packbf(float a, float b) {
    __nv_bfloat162 h = __floats2bfloat162_rn(a, b);
    return *(uint32_t*)&h;
}

// 16-wide log-semiring matvec step (smem exchange among 16 converged lanes).
__device__ __forceinline__ float lse_step(
    float alpha, int jj, float* sA, float* sEa,
    float4 P0, float4 P1, float4 P2, float4 P3)
{
    sA[jj] = alpha;
    __syncwarp(0xffffu);
    const float m  = sA[0];
    const float ea = __expf(alpha - m);
    sEa[jj] = ea;
    __syncwarp(0xffffu);
    const float4 e0 = *(const float4*)(sEa + 0);
    const float4 e1 = *(const float4*)(sEa + 4);
    const float4 e2 = *(const float4*)(sEa + 8);
    const float4 e3 = *(const float4*)(sEa + 12);
    float s0 = e0.x * P0.x, s1 = e0.y * P0.y, s2 = e0.z * P0.z, s3 = e0.w * P0.w;
    s0 = fmaf(e1.x, P1.x, s0); s1 = fmaf(e1.y, P1.y, s1);
    s2 = fmaf(e1.z, P1.z, s2); s3 = fmaf(e1.w, P1.w, s3);
    s0 = fmaf(e2.x, P2.x, s0); s1 = fmaf(e2.y, P2.y, s1);
    s2 = fmaf(e2.z, P2.z, s2); s3 = fmaf(e2.w, P2.w, s3);
    s0 = fmaf(e3.x, P3.x, s0); s1 = fmaf(e3.y, P3.y, s1);
    s2 = fmaf(e3.z, P3.z, s2); s3 = fmaf(e3.w, P3.w, s3);
    return m + __logf((s0 + s1) + (s2 + s3));
}

// ---------------------------------------------------------------------------
// Fused prep kernel (one launch)
// ---------------------------------------------------------------------------
#define PREP_CONVX   16384
#define PREP_INITEM  (PREP_CONVX + 512)
#define PREP_TOTAL   (PREP_INITEM + 256)

__global__ __launch_bounds__(256) void prep_kernel(
    const float* __restrict__ X, const float* __restrict__ W1,
    const float* __restrict__ b2, float* __restrict__ out)
{
    const int bid = blockIdx.x;
    const int tid = threadIdx.x;

    if (bid < PREP_CONVX) {
        size_t i = ((size_t)bid * 256 + tid) * 4;
        float4 v = *(const float4*)(X + i);
        uint2 u;
        u.x = packbf(v.x, v.y);
        u.y = packbf(v.z, v.w);
        *(uint2*)(g_Xb + i) = u;
    } else if (bid < PREP_INITEM) {
        if (bid == PREP_CONVX && tid == 0) out[0] = 0.f;
        size_t i = ((size_t)(bid - PREP_CONVX) * 256 + tid) * 4;
        const int ph = (int)(i & 15);
        float4 v;
        v.x = b2[ph]; v.y = b2[ph + 1]; v.z = b2[ph + 2]; v.w = b2[ph + 3];
        *(float4*)(g_em + i) = v;
    } else {
        __shared__ float t[32][33];
        const int tb = bid - PREP_INITEM;
        const int bx = (tb & 15) * 32, by = (tb >> 4) * 32;
        const int x = tid & 31, y = tid >> 5;   // 32 x 8
#pragma unroll
        for (int i = 0; i < 4; i++)
            t[y + i * 8][x] = W1[(size_t)(by + y + i * 8) * H_ + bx + x];
        __syncthreads();
#pragma unroll
        for (int i = 0; i < 4; i++)
            g_W1T[(size_t)(bx + y + i * 8) * H_ + by + x] =
                __float2bfloat16(t[x][y + i * 8]);
    }
}

// ---------------------------------------------------------------------------
// K1: fused  h = relu(X@W1+b1);  em += h @ W2   (unchanged; passing since R7)
// ---------------------------------------------------------------------------
#define BM 128
#define BN 128
#define BK 32
#define NKC (H_/BK)           // 16
#define ROWW 20
#define TILE_WORDS (BM*ROWW)
#define STAGE_WORDS (2*TILE_WORDS)
#define SMEM_BYTES (4*STAGE_WORDS*4)   // 81920

__global__ __launch_bounds__(256, 2) void gemm1_fused(
    const float* __restrict__ b1, const float* __restrict__ W2)
{
    extern __shared__ uint32_t sw[];
    const uint32_t sb = smem_u32(sw);
    const int tid  = threadIdx.x;
    const int wid  = tid >> 5, lane = tid & 31;
    const int g    = lane >> 2, t = lane & 3;
    const int wm   = wid >> 2;
    const int wn   = wid & 3;
    const int ks   = wid & 1;
    const int row0 = blockIdx.y * BM;
    const int col0 = blockIdx.x * BN;

    auto issue_stage = [&](int c, int s) {
        const int k0 = c * BK;
        const uint32_t base = (uint32_t)(s * STAGE_WORDS);
#pragma unroll
        for (int q = 0; q < 2; q++) {
            const int u   = tid + q * 256;
            const int row = u >> 2, seg = u & 3;
            cp_async16(sb + (base + row * ROWW + seg * 4) * 4,
                       g_Xb + (size_t)(row0 + row) * H_ + k0 + seg * 8);
        }
#pragma unroll
        for (int q = 0; q < 2; q++) {
            const int u   = tid + q * 256;
            const int row = u >> 2, seg = u & 3;
            cp_async16(sb + (base + TILE_WORDS + row * ROWW + seg * 4) * 4,
                       g_W1T + (size_t)(col0 + row) * H_ + k0 + seg * 8);
        }
    };

    issue_stage(0, 0); CP_COMMIT();
    issue_stage(1, 1); CP_COMMIT();
    issue_stage(2, 2); CP_COMMIT();

    const int r8    = lane & 7;
    const int aWOff = ((wm * 64 + r8 + (((lane >> 3) & 1) << 3)) * ROWW)
                    + ((lane >> 4) << 2);
    const int bWOff = TILE_WORDS
                    + ((wn * 32 + r8 + (((lane >> 4) & 1) << 3)) * ROWW)
                    + (((lane >> 3) & 1) << 2);

    float acc[4][4][4];
#pragma unroll
    for (int i = 0; i < 4; i++)
#pragma unroll
        for (int j = 0; j < 4; j++)
#pragma unroll
            for (int r = 0; r < 4; r++) acc[i][j][r] = 0.f;

    for (int c = 0; c < NKC; c++) {
        if (c <= NKC - 3)      CP_WAIT(2);
        else if (c == NKC - 2) CP_WAIT(1);
        else                   CP_WAIT(0);
        __syncthreads();
        if (c + 3 < NKC) { issue_stage(c + 3, (c + 3) & 3); CP_COMMIT(); }

        const uint32_t stg = sb + (uint32_t)(c & 3) * (STAGE_WORDS * 4);

#pragma unroll
        for (int kk2 = 0; kk2 < 2; kk2++) {
            const int kk = kk2 ^ ks;
            const int kw = kk * 8;
            uint32_t af[4][4], bf[4][2];
#pragma unroll
            for (int i = 0; i < 4; i++)
                ldsm_x4(af[i], stg + (uint32_t)(aWOff + i * 16 * ROWW + kw) * 4);
#pragma unroll
            for (int p = 0; p < 2; p++) {
                uint32_t br[4];
                ldsm_x4(br, stg + (uint32_t)(bWOff + p * 16 * ROWW + kw) * 4);
                bf[2*p][0]   = br[0]; bf[2*p][1]   = br[1];
                bf[2*p+1][0] = br[2]; bf[2*p+1][1] = br[3];
            }
#pragma unroll
            for (int i = 0; i < 4; i++)
#pragma unroll
                for (int j = 0; j < 4; j++)
                    mma16816(acc[i][j], af[i], bf[j]);
        }
    }

#pragma unroll
    for (int j = 0; j < 4; j++) {
        const int col = col0 + wn * 32 + j * 8 + 2 * t;
        const float bb0 = __ldg(b1 + col), bb1 = __ldg(b1 + col + 1);
#pragma unroll
        for (int i = 0; i < 4; i++) {
            acc[i][j][0] = fmaxf(acc[i][j][0] + bb0, 0.f);
            acc[i][j][1] = fmaxf(acc[i][j][1] + bb1, 0.f);
            acc[i][j][2] = fmaxf(acc[i][j][2] + bb0, 0.f);
            acc[i][j][3] = fmaxf(acc[i][j][3] + bb1, 0.f);
        }
    }

    uint32_t bw[2][2][2];
    {
        const int kb0 = col0 + wn * 32;
#pragma unroll
        for (int jp = 0; jp < 2; jp++)
#pragma unroll
            for (int nt = 0; nt < 2; nt++) {
                const int kb = kb0 + jp * 16;
                const int n  = nt * 8 + g;
                float w0 = __ldg(W2 + (size_t)(kb + 2*t)     * KK_ + n);
                float w1 = __ldg(W2 + (size_t)(kb + 2*t + 1) * KK_ + n);
                float w2v= __ldg(W2 + (size_t)(kb + 2*t + 8) * KK_ + n);
                float w3 = __ldg(W2 + (size_t)(kb + 2*t + 9) * KK_ + n);
                bw[jp][nt][0] = packbf(w0, w1);
                bw[jp][nt][1] = packbf(w2v, w3);
            }
    }

    __syncthreads();
    float* em_s = (float*)sw;

#pragma unroll
    for (int i = 0; i < 4; i++) {
        float e0[4] = {0.f, 0.f, 0.f, 0.f};
        float e1[4] = {0.f, 0.f, 0.f, 0.f};
#pragma unroll
        for (int jp = 0; jp < 2; jp++) {
            uint32_t af_[4];
            af_[0] = packbf(acc[i][2*jp][0],   acc[i][2*jp][1]);
            af_[1] = packbf(acc[i][2*jp][2],   acc[i][2*jp][3]);
            af_[2] = packbf(acc[i][2*jp+1][0], acc[i][2*jp+1][1]);
            af_[3] = packbf(acc[i][2*jp+1][2], acc[i][2*jp+1][3]);
            mma16816(e0, af_, bw[jp][0]);
            mma16816(e1, af_, bw[jp][1]);
        }
        const int r = wm * 64 + i * 16 + g;
        float* sl  = em_s + (size_t)(wn * 128 + r) * 18;
        float* sl8 = em_s + (size_t)(wn * 128 + r + 8) * 18;
        *(float2*)(sl  + 2*t)     = make_float2(e0[0], e0[1]);
        *(float2*)(sl  + 8 + 2*t) = make_float2(e1[0], e1[1]);
        *(float2*)(sl8 + 2*t)     = make_float2(e0[2], e0[3]);
        *(float2*)(sl8 + 8 + 2*t) = make_float2(e1[2], e1[3]);
    }
    __syncthreads();

#pragma unroll
    for (int q = 0; q < 8; q++) {
        const int o = tid + q * 256;
        const int r = o >> 4, n = o & 15;
        float s = em_s[(size_t)(0 * 128 + r) * 18 + n]
                + em_s[(size_t)(1 * 128 + r) * 18 + n]
                + em_s[(size_t)(2 * 128 + r) * 18 + n]
                + em_s[(size_t)(3 * 128 + r) * 18 + n];
        atomicAdd(g_em + (size_t)(row0 + r) * KK_ + n, s);
    }
}

// ---------------------------------------------------------------------------
// Scan phase 1: 16-step chunk matrices (smem-exchange chains).
// ---------------------------------------------------------------------------
__global__ __launch_bounds__(256) void scan_p1(const float* __restrict__ trans)
{
    const int c = blockIdx.x, b = blockIdx.y;
    const int tid  = threadIdx.x;
    const int wid  = tid >> 5, lane = tid & 31;
    const int jj   = lane & 15;
    const int col  = wid * 2 + (lane >> 4);

    __shared__ float es[16][16];
    __shared__ float cm[16][17];
    __shared__ __align__(16) float xA[16][16];
    __shared__ __align__(16) float xE[16][16];

    {
        const int tt = tid >> 4, k = tid & 15;
        es[tt][k] = g_em[(size_t)((16*c + 1 + tt) * B_ + b) * KK_ + k];
    }
    float4 T0, T1, T2, T3;
    {
        float te[16];
#pragma unroll
        for (int i = 0; i < 16; i++)
            te[i] = __expf(trans[jj * KK_ + i]);
        T0 = make_float4(te[0], te[1], te[2], te[3]);
        T1 = make_float4(te[4], te[5], te[6], te[7]);
        T2 = make_float4(te[8], te[9], te[10], te[11]);
        T3 = make_float4(te[12], te[13], te[14], te[15]);
    }
    const float tr_col = trans[jj * KK_ + col];
    __syncthreads();

    float v = tr_col + es[0][jj];
#pragma unroll
    for (int tt = 1; tt < 16; tt++) {
        float vn = lse_step(v, jj, xA[col], xE[col], T0, T1, T2, T3);
        v = vn + es[tt][jj];
    }
    cm[col][jj] = v;
    __syncthreads();

    if (tid < 16) {
        float r[16];
        float rm = -3.0e38f;
#pragma unroll
        for (int i = 0; i < 16; i++) {
            r[i] = cm[i][tid];
            rm = fmaxf(rm, r[i]);
        }
        float out4[16];
#pragma unroll
        for (int i = 0; i < 16; i++)
            out4[i] = __expf(r[i] - rm);
        float* dst = g_P + (size_t)((b * NCHK + c) * 16 + tid) * 16;
#pragma unroll
        for (int q = 0; q < 4; q++)
            *(float4*)(dst + q * 4) =
                make_float4(out4[4*q], out4[4*q+1], out4[4*q+2], out4[4*q+3]);
        g_R[(b * NCHK + c) * 16 + tid] = rm;
    }
}

// ---------------------------------------------------------------------------
// Pair kernel: 32-step matrices.  M32[c] = M[2c+1] o M[2c]  (log-semiring).
// grid (NP2, B_), 256 threads; one output element (j,i) per thread.
// ---------------------------------------------------------------------------
__global__ __launch_bounds__(256) void pair_kernel()
{
    const int c = blockIdx.x, b = blockIdx.y;
    const int tid = threadIdx.x;
    const int r = tid >> 4, q = tid & 15;   // j = r, i = q

    __shared__ float LA[16][17];   // log M[2c]   : [k][i]
    __shared__ float LB[16][17];   // log M[2c+1] : [j][k]
    __shared__ float C[16][17];

    LA[r][q] = __logf(g_P[(size_t)((b * NCHK + 2*c)     * 16 + r) * 16 + q])
             + g_R[(b * NCHK + 2*c) * 16 + r];
    LB[r][q] = __logf(g_P[(size_t)((b * NCHK + 2*c + 1) * 16 + r) * 16 + q])
             + g_R[(b * NCHK + 2*c + 1) * 16 + r];
    __syncthreads();

    float m = LB[r][0] + LA[0][q];
#pragma unroll
    for (int k = 1; k < 16; k++)
        m = fmaxf(m, LB[r][k] + LA[k][q]);
    float s = 0.f;
#pragma unroll
    for (int k = 0; k < 16; k++)
        s += __expf(LB[r][k] + LA[k][q] - m);
    C[r][q] = m + __logf(s);
    __syncthreads();

    if (tid < 16) {
        float rr[16];
        float rm = -3.0e38f;
#pragma unroll
        for (int i = 0; i < 16; i++) {
            rr[i] = C[tid][i];
            rm = fmaxf(rm, rr[i]);
        }
        float o[16];
#pragma unroll
        for (int i = 0; i < 16; i++)
            o[i] = __expf(rr[i] - rm);
        float* dst = g_P32 + (size_t)((b * NP2 + c) * 16 + tid) * 16;
#pragma unroll
        for (int u = 0; u < 4; u++)
            *(float4*)(dst + u * 4) =
                make_float4(o[4*u], o[4*u+1], o[4*u+2], o[4*u+3]);
        g_R32[(b * NP2 + c) * 16 + tid] = rm;
    }
}

// ---------------------------------------------------------------------------
// Scan phase 2: fully-unrolled predicated combine (<=31 serial steps).
// ---------------------------------------------------------------------------
__global__ __launch_bounds__(64) void scan_p2(
    const float* __restrict__ trans, const int* __restrict__ lens,
    const int* __restrict__ tags, float* __restrict__ out)
{
    const int b   = blockIdx.x;
    const int tid = threadIdx.x;
    const unsigned F = 0xffffffffu;
    const int len   = lens[b];
    const int last  = len - 1;
    const int nfull = last >> 4;       // 15..31
    const int nrem  = last & 15;
    const int nf32  = nfull >> 1;      // 7..15
    const int odd   = nfull & 1;

    __shared__ float sOut[2];
    __shared__ __align__(16) float sA[16];
    __shared__ __align__(16) float sEa[16];

    if (tid < 16) {
        const int jj = tid;
        float4 T0, T1, T2, T3;
        {
            float te[16];
#pragma unroll
            for (int i = 0; i < 16; i++)
                te[i] = __expf(trans[jj * KK_ + i]);
            T0 = make_float4(te[0], te[1], te[2], te[3]);
            T1 = make_float4(te[4], te[5], te[6], te[7]);
            T2 = make_float4(te[8], te[9], te[10], te[11]);
            T3 = make_float4(te[12], te[13], te[14], te[15]);
        }

        float alpha = g_em[(size_t)(0 * B_ + b) * KK_ + jj];

        // ---- 32-step combines, fully unrolled, predicated commit ----
#pragma unroll
        for (int c = 0; c < NP2; c++) {
            const float* src = g_P32 + ((size_t)(b * NP2 + c) * 16 + jj) * 16;
            const float4 P0 = *(const float4*)(src);
            const float4 P1 = *(const float4*)(src + 4);
            const float4 P2 = *(const float4*)(src + 8);
            const float4 P3 = *(const float4*)(src + 12);
            const float  Rc = g_R32[(b * NP2 + c) * 16 + jj];
            const float cand = lse_step(alpha, jj, sA, sEa, P0, P1, P2, P3) + Rc;
            alpha = (c < nf32) ? cand : alpha;
        }

        // ---- odd 16-step chunk (index 2*nf32), predicated ----
        {
            const int co = 2 * nf32;   // <= 30
            const float* src = g_P + ((size_t)(b * NCHK + co) * 16 + jj) * 16;
            const float4 P0 = *(const float4*)(src);
            const float4 P1 = *(const float4*)(src + 4);
            const float4 P2 = *(const float4*)(src + 8);
            const float4 P3 = *(const float4*)(src + 12);
            const float  Rc = g_R[(b * NCHK + co) * 16 + jj];
            const float cand = lse_step(alpha, jj, sA, sEa, P0, P1, P2, P3) + Rc;
            alpha = odd ? cand : alpha;
        }

        // ---- elementary remainder steps, fully unrolled, predicated ----
#pragma unroll
        for (int s = 0; s < 15; s++) {
            int tt = 16 * nfull + 1 + s;
            tt = (tt < T_) ? tt : (T_ - 1);
            const float e = g_em[(size_t)(tt * B_ + b) * KK_ + jj];
            const float cand = lse_step(alpha, jj, sA, sEa, T0, T1, T2, T3) + e;
            alpha = (s < nrem) ? cand : alpha;
        }

        float m2 = alpha;
#pragma unroll
        for (int off = 8; off; off >>= 1)
            m2 = fmaxf(m2, __shfl_xor_sync(0xffffu, m2, off, 16));
        float ss = __expf(alpha - m2);
#pragma unroll
        for (int off = 8; off; off >>= 1)
            ss += __shfl_xor_sync(0xffffu, ss, off, 16);
        if (jj == 0) sOut[0] = m2 + __logf(ss);
    } else if (tid >= 32) {
        const int lane = tid - 32;
        float g = 0.f;
#pragma unroll
        for (int t = 0; t < 16; t++) {
            const int tt = lane + t * 32;
            if (tt < len) {
                const int tag = tags[tt * B_ + b];
                float v = g_em[(size_t)(tt * B_ + b) * KK_ + tag];
                if (tt > 0) {
                    const int tp = tags[(tt - 1) * B_ + b];
                    v += trans[tag * KK_ + tp];
                }
                g += v;
            }
        }
#pragma unroll
        for (int off = 16; off; off >>= 1)
            g += __shfl_xor_sync(F, g, off);
        if (lane == 0) sOut[1] = g;
    }
    __syncthreads();
    if (tid == 0) atomicAdd(out, sOut[0] - sOut[1]);
}

// ---------------------------------------------------------------------------
extern "C" void kernel_launch(void* const* d_in, const int* in_sizes, int n_in,
                              void* d_out, int out_size)
{
    (void)in_sizes; (void)n_in; (void)out_size;
    const float* hidden = (const float*)d_in[0];
    const float* W1     = (const float*)d_in[1];
    const float* b1     = (const float*)d_in[2];
    const float* W2     = (const float*)d_in[3];
    const float* b2     = (const float*)d_in[4];
    const float* trans  = (const float*)d_in[5];
    const int*   lens   = (const int*)d_in[6];
    const int*   tags   = (const int*)d_in[7];

    cudaFuncSetAttribute(gemm1_fused, cudaFuncAttributeMaxDynamicSharedMemorySize,
                         SMEM_BYTES);

    prep_kernel<<<PREP_TOTAL, 256>>>(hidden, W1, b2, (float*)d_out);
    gemm1_fused<<<dim3(H_ / BN, M_ / BM), 256, SMEM_BYTES>>>(b1, W2);
    scan_p1<<<dim3(NCHK, B_), 256>>>(trans);
    pair_kernel<<<dim3(NP2, B_), 256>>>();
    scan_p2<<<B_, 64>>>(trans, lens, tags, (float*)d_out);
}

// round 11
// speedup vs baseline: 1.5779x; 1.5779x over previous
#include <cuda_runtime.h>
#include <cuda_bf16.h>
#include <cstdint>
#include <math.h>

#define T_ 512
#define B_ 64
#define H_ 512
#define KK_ 16
#define M_ (T_*B_)       // 32768
#define NCHK 31          // 16-step chunk matrices per batch
#define NP2  15          // 32-step (paired) matrices per batch

// ---------------- device scratch (allocation-free rule) ----------------
__device__ __nv_bfloat16 g_Xb[M_ * H_];    // 32 MB  X in bf16
__device__ __nv_bfloat16 g_W1T[H_ * H_];   // 0.5 MB W1^T in bf16
__device__ float g_em[M_ * KK_];           // 2 MB emissions (atomic-accumulated)
__device__ float g_P[B_ * NCHK * 16 * 16]; // 16-step matrices, exp-form (global-max norm)
__device__ float g_R[B_ * NCHK];           // matrix-global log offsets
__device__ float g_P32[B_ * NP2 * 16 * 16];// 32-step matrices, exp-form
__device__ float g_R32[B_ * NP2];          // matrix-global log offsets

// ---------------- helpers ----------------
__device__ __forceinline__ uint32_t smem_u32(const void* p) {
    uint32_t a;
    asm("{ .reg .u64 t; cvta.to.shared.u64 t, %1; cvt.u32.u64 %0, t; }"
        : "=r"(a) : "l"(p));
    return a;
}
__device__ __forceinline__ void cp_async16(uint32_t dst, const void* src) {
    asm volatile("cp.async.cg.shared.global [%0], [%1], 16;\n" :: "r"(dst), "l"(src));
}
#define CP_COMMIT() asm volatile("cp.async.commit_group;\n" ::: "memory")
#define CP_WAIT(n)  asm volatile("cp.async.wait_group %0;\n" :: "n"(n) : "memory")

__device__ __forceinline__ void mma16816(float* d, const uint32_t* a, const uint32_t* b) {
    asm volatile(
        "mma.sync.aligned.m16n8k16.row.col.f32.bf16.bf16.f32 "
        "{%0,%1,%2,%3}, {%4,%5,%6,%7}, {%8,%9}, {%0,%1,%2,%3};\n"
        : "+f"(d[0]), "+f"(d[1]), "+f"(d[2]), "+f"(d[3])
        : "r"(a[0]), "r"(a[1]), "r"(a[2]), "r"(a[3]), "r"(b[0]), "r"(b[1]));
}
__device__ __forceinline__ void ldsm_x4(uint32_t* r, uint32_t addr) {
    asm volatile("ldmatrix.sync.aligned.m8n8.x4.shared.b16 {%0,%1,%2,%3}, [%4];\n"
                 : "=r"(r[0]), "=r"(r[1]), "=r"(r[2]), "=r"(r[3]) : "r"(addr));
}
__device__ __forceinline__ uint32_t packbf(float a, float b) {
    __nv_bfloat162 h = __floats2bfloat162_rn(a, b);
    return *(uint32_t*)&h;
}
__device__ __forceinline__ float dot16(
    float4 a0, float4 a1, float4 a2, float4 a3,
    float4 b0, float4 b1, float4 b2, float4 b3)
{
    float s0 = a0.x * b0.x, s1 = a0.y * b0.y, s2 = a0.z * b0.z, s3 = a0.w * b0.w;
    s0 = fmaf(a1.x, b1.x, s0); s1 = fmaf(a1.y, b1.y, s1);
    s2 = fmaf(a1.z, b1.z, s2); s3 = fmaf(a1.w, b1.w, s3);
    s0 = fmaf(a2.x, b2.x, s0); s1 = fmaf(a2.y, b2.y, s1);
    s2 = fmaf(a2.z, b2.z, s2); s3 = fmaf(a2.w, b2.w, s3);
    s0 = fmaf(a3.x, b3.x, s0); s1 = fmaf(a3.y, b3.y, s1);
    s2 = fmaf(a3.z, b3.z, s2); s3 = fmaf(a3.w, b3.w, s3);
    return (s0 + s1) + (s2 + s3);
}

// ---------------------------------------------------------------------------
// Fused prep kernel (one launch)
// ---------------------------------------------------------------------------
#define PREP_CONVX   16384
#define PREP_INITEM  (PREP_CONVX + 512)
#define PREP_TOTAL   (PREP_INITEM + 256)

__global__ __launch_bounds__(256) void prep_kernel(
    const float* __restrict__ X, const float* __restrict__ W1,
    const float* __restrict__ b2, float* __restrict__ out)
{
    const int bid = blockIdx.x;
    const int tid = threadIdx.x;

    if (bid < PREP_CONVX) {
        size_t i = ((size_t)bid * 256 + tid) * 4;
        float4 v = *(const float4*)(X + i);
        uint2 u;
        u.x = packbf(v.x, v.y);
        u.y = packbf(v.z, v.w);
        *(uint2*)(g_Xb + i) = u;
    } else if (bid < PREP_INITEM) {
        if (bid == PREP_CONVX && tid == 0) out[0] = 0.f;
        size_t i = ((size_t)(bid - PREP_CONVX) * 256 + tid) * 4;
        const int ph = (int)(i & 15);
        float4 v;
        v.x = b2[ph]; v.y = b2[ph + 1]; v.z = b2[ph + 2]; v.w = b2[ph + 3];
        *(float4*)(g_em + i) = v;
    } else {
        __shared__ float t[32][33];
        const int tb = bid - PREP_INITEM;
        const int bx = (tb & 15) * 32, by = (tb >> 4) * 32;
        const int x = tid & 31, y = tid >> 5;   // 32 x 8
#pragma unroll
        for (int i = 0; i < 4; i++)
            t[y + i * 8][x] = W1[(size_t)(by + y + i * 8) * H_ + bx + x];
        __syncthreads();
#pragma unroll
        for (int i = 0; i < 4; i++)
            g_W1T[(size_t)(bx + y + i * 8) * H_ + by + x] =
                __float2bfloat16(t[x][y + i * 8]);
    }
}

// ---------------------------------------------------------------------------
// K1: fused  h = relu(X@W1+b1);  em += h @ W2   (unchanged; passing since R7)
// ---------------------------------------------------------------------------
#define BM 128
#define BN 128
#define BK 32
#define NKC (H_/BK)           // 16
#define ROWW 20
#define TILE_WORDS (BM*ROWW)
#define STAGE_WORDS (2*TILE_WORDS)
#define SMEM_BYTES (4*STAGE_WORDS*4)   // 81920

__global__ __launch_bounds__(256, 2) void gemm1_fused(
    const float* __restrict__ b1, const float* __restrict__ W2)
{
    extern __shared__ uint32_t sw[];
    const uint32_t sb = smem_u32(sw);
    const int tid  = threadIdx.x;
    const int wid  = tid >> 5, lane = tid & 31;
    const int g    = lane >> 2, t = lane & 3;
    const int wm   = wid >> 2;
    const int wn   = wid & 3;
    const int ks   = wid & 1;
    const int row0 = blockIdx.y * BM;
    const int col0 = blockIdx.x * BN;

    auto issue_stage = [&](int c, int s) {
        const int k0 = c * BK;
        const uint32_t base = (uint32_t)(s * STAGE_WORDS);
#pragma unroll
        for (int q = 0; q < 2; q++) {
            const int u   = tid + q * 256;
            const int row = u >> 2, seg = u & 3;
            cp_async16(sb + (base + row * ROWW + seg * 4) * 4,
                       g_Xb + (size_t)(row0 + row) * H_ + k0 + seg * 8);
        }
#pragma unroll
        for (int q = 0; q < 2; q++) {
            const int u   = tid + q * 256;
            const int row = u >> 2, seg = u & 3;
            cp_async16(sb + (base + TILE_WORDS + row * ROWW + seg * 4) * 4,
                       g_W1T + (size_t)(col0 + row) * H_ + k0 + seg * 8);
        }
    };

    issue_stage(0, 0); CP_COMMIT();
    issue_stage(1, 1); CP_COMMIT();
    issue_stage(2, 2); CP_COMMIT();

    const int r8    = lane & 7;
    const int aWOff = ((wm * 64 + r8 + (((lane >> 3) & 1) << 3)) * ROWW)
                    + ((lane >> 4) << 2);
    const int bWOff = TILE_WORDS
                    + ((wn * 32 + r8 + (((lane >> 4) & 1) << 3)) * ROWW)
                    + (((lane >> 3) & 1) << 2);

    float acc[4][4][4];
#pragma unroll
    for (int i = 0; i < 4; i++)
#pragma unroll
        for (int j = 0; j < 4; j++)
#pragma unroll
            for (int r = 0; r < 4; r++) acc[i][j][r] = 0.f;

    for (int c = 0; c < NKC; c++) {
        if (c <= NKC - 3)      CP_WAIT(2);
        else if (c == NKC - 2) CP_WAIT(1);
        else                   CP_WAIT(0);
        __syncthreads();
        if (c + 3 < NKC) { issue_stage(c + 3, (c + 3) & 3); CP_COMMIT(); }

        const uint32_t stg = sb + (uint32_t)(c & 3) * (STAGE_WORDS * 4);

#pragma unroll
        for (int kk2 = 0; kk2 < 2; kk2++) {
            const int kk = kk2 ^ ks;
            const int kw = kk * 8;
            uint32_t af[4][4], bf[4][2];
#pragma unroll
            for (int i = 0; i < 4; i++)
                ldsm_x4(af[i], stg + (uint32_t)(aWOff + i * 16 * ROWW + kw) * 4);
#pragma unroll
            for (int p = 0; p < 2; p++) {
                uint32_t br[4];
                ldsm_x4(br, stg + (uint32_t)(bWOff + p * 16 * ROWW + kw) * 4);
                bf[2*p][0]   = br[0]; bf[2*p][1]   = br[1];
                bf[2*p+1][0] = br[2]; bf[2*p+1][1] = br[3];
            }
#pragma unroll
            for (int i = 0; i < 4; i++)
#pragma unroll
                for (int j = 0; j < 4; j++)
                    mma16816(acc[i][j], af[i], bf[j]);
        }
    }

#pragma unroll
    for (int j = 0; j < 4; j++) {
        const int col = col0 + wn * 32 + j * 8 + 2 * t;
        const float bb0 = __ldg(b1 + col), bb1 = __ldg(b1 + col + 1);
#pragma unroll
        for (int i = 0; i < 4; i++) {
            acc[i][j][0] = fmaxf(acc[i][j][0] + bb0, 0.f);
            acc[i][j][1] = fmaxf(acc[i][j][1] + bb1, 0.f);
            acc[i][j][2] = fmaxf(acc[i][j][2] + bb0, 0.f);
            acc[i][j][3] = fmaxf(acc[i][j][3] + bb1, 0.f);
        }
    }

    uint32_t bw[2][2][2];
    {
        const int kb0 = col0 + wn * 32;
#pragma unroll
        for (int jp = 0; jp < 2; jp++)
#pragma unroll
            for (int nt = 0; nt < 2; nt++) {
                const int kb = kb0 + jp * 16;
                const int n  = nt * 8 + g;
                float w0 = __ldg(W2 + (size_t)(kb + 2*t)     * KK_ + n);
                float w1 = __ldg(W2 + (size_t)(kb + 2*t + 1) * KK_ + n);
                float w2v= __ldg(W2 + (size_t)(kb + 2*t + 8) * KK_ + n);
                float w3 = __ldg(W2 + (size_t)(kb + 2*t + 9) * KK_ + n);
                bw[jp][nt][0] = packbf(w0, w1);
                bw[jp][nt][1] = packbf(w2v, w3);
            }
    }

    __syncthreads();
    float* em_s = (float*)sw;

#pragma unroll
    for (int i = 0; i < 4; i++) {
        float e0[4] = {0.f, 0.f, 0.f, 0.f};
        float e1[4] = {0.f, 0.f, 0.f, 0.f};
#pragma unroll
        for (int jp = 0; jp < 2; jp++) {
            uint32_t af_[4];
            af_[0] = packbf(acc[i][2*jp][0],   acc[i][2*jp][1]);
            af_[1] = packbf(acc[i][2*jp][2],   acc[i][2*jp][3]);
            af_[2] = packbf(acc[i][2*jp+1][0], acc[i][2*jp+1][1]);
            af_[3] = packbf(acc[i][2*jp+1][2], acc[i][2*jp+1][3]);
            mma16816(e0, af_, bw[jp][0]);
            mma16816(e1, af_, bw[jp][1]);
        }
        const int r = wm * 64 + i * 16 + g;
        float* sl  = em_s + (size_t)(wn * 128 + r) * 18;
        float* sl8 = em_s + (size_t)(wn * 128 + r + 8) * 18;
        *(float2*)(sl  + 2*t)     = make_float2(e0[0], e0[1]);
        *(float2*)(sl  + 8 + 2*t) = make_float2(e1[0], e1[1]);
        *(float2*)(sl8 + 2*t)     = make_float2(e0[2], e0[3]);
        *(float2*)(sl8 + 8 + 2*t) = make_float2(e1[2], e1[3]);
    }
    __syncthreads();

#pragma unroll
    for (int q = 0; q < 8; q++) {
        const int o = tid + q * 256;
        const int r = o >> 4, n = o & 15;
        float s = em_s[(size_t)(0 * 128 + r) * 18 + n]
                + em_s[(size_t)(1 * 128 + r) * 18 + n]
                + em_s[(size_t)(2 * 128 + r) * 18 + n]
                + em_s[(size_t)(3 * 128 + r) * 18 + n];
        atomicAdd(g_em + (size_t)(row0 + r) * KK_ + n, s);
    }
}

// ---------------------------------------------------------------------------
// Scan phase 1: 16-step chunk matrices via linear-space chains.
// 16 chains (source states) per block; output exp-form, matrix-global norm.
// ---------------------------------------------------------------------------
__global__ __launch_bounds__(256) void scan_p1(const float* __restrict__ trans)
{
    const int c = blockIdx.x, b = blockIdx.y;
    const int tid  = threadIdx.x;
    const int wid  = tid >> 5, lane = tid & 31;
    const int jj   = lane & 15;
    const int col  = wid * 2 + (lane >> 4);

    __shared__ float es[16][16];
    __shared__ float cm[16][17];
    __shared__ float rms[16];
    __shared__ __align__(16) float xW[2][16][16];

    {
        const int tt = tid >> 4, k = tid & 15;
        es[tt][k] = g_em[(size_t)((16*c + 1 + tt) * B_ + b) * KK_ + k];
    }
    // Texp = exp(trans_row_jj - maxT)
    float Trow[16];
#pragma unroll
    for (int i = 0; i < 16; i++) Trow[i] = trans[jj * KK_ + i];
    float maxT = Trow[0];
#pragma unroll
    for (int i = 1; i < 16; i++) maxT = fmaxf(maxT, Trow[i]);
#pragma unroll
    for (int off = 8; off; off >>= 1)
        maxT = fmaxf(maxT, __shfl_xor_sync(0xffffffffu, maxT, off, 16));
    float4 T0, T1, T2, T3;
    {
        float te[16];
#pragma unroll
        for (int i = 0; i < 16; i++) te[i] = __expf(Trow[i] - maxT);
        T0 = make_float4(te[0], te[1], te[2], te[3]);
        T1 = make_float4(te[4], te[5], te[6], te[7]);
        T2 = make_float4(te[8], te[9], te[10], te[11]);
        T3 = make_float4(te[12], te[13], te[14], te[15]);
    }
    const float tr_own = trans[jj * KK_ + col];
    const float tr_0   = trans[col];            // trans[0][col]
    __syncthreads();

    // init: alpha_j = trans[j][col] + es[0][j];  L = alpha_0
    float L = tr_0 + es[0][0];
    float w_own = __expf(tr_own + es[0][jj] - L);
    xW[0][col][jj] = w_own;
    __syncwarp(0xffffffffu);
    float4 t0 = *(const float4*)(xW[0][col] + 0);
    float4 t1 = *(const float4*)(xW[0][col] + 4);
    float4 t2 = *(const float4*)(xW[0][col] + 8);
    float4 t3 = *(const float4*)(xW[0][col] + 12);
    float rcp_last = 1.f;
    int pb = 1;

#pragma unroll 1
    for (int tt = 1; tt < 16; tt++) {
        const float em0 = es[tt][0];
        const float esc = __expf(es[tt][jj] - em0);
        float w = dot16(t0, t1, t2, t3, T0, T1, T2, T3) * esc;
        xW[pb][col][jj] = w;
        __syncwarp(0xffffffffu);
        const float w0 = xW[pb][col][0];
        const float rcp = __fdividef(1.f, w0);
        L += maxT + em0 + __logf(w0);
        float4 u0 = *(const float4*)(xW[pb][col] + 0);
        float4 u1 = *(const float4*)(xW[pb][col] + 4);
        float4 u2 = *(const float4*)(xW[pb][col] + 8);
        float4 u3 = *(const float4*)(xW[pb][col] + 12);
        t0 = make_float4(u0.x*rcp, u0.y*rcp, u0.z*rcp, u0.w*rcp);
        t1 = make_float4(u1.x*rcp, u1.y*rcp, u1.z*rcp, u1.w*rcp);
        t2 = make_float4(u2.x*rcp, u2.y*rcp, u2.z*rcp, u2.w*rcp);
        t3 = make_float4(u3.x*rcp, u3.y*rcp, u3.z*rcp, u3.w*rcp);
        w_own = w; rcp_last = rcp;
        pb ^= 1;
    }
    // own log value: alpha[jj] = L + log(w_own * rcp_last)
    cm[col][jj] = L + __logf(w_own * rcp_last);
    __syncthreads();

    if (tid < 16) {
        float rm = cm[0][tid];
#pragma unroll
        for (int i = 1; i < 16; i++) rm = fmaxf(rm, cm[i][tid]);
        rms[tid] = rm;
    }
    __syncthreads();
    if (tid < 16) {
        float gmax = rms[0];
#pragma unroll
        for (int i = 1; i < 16; i++) gmax = fmaxf(gmax, rms[i]);
        float o[16];
#pragma unroll
        for (int i = 0; i < 16; i++)
            o[i] = __expf(cm[i][tid] - gmax);
        float* dst = g_P + (size_t)((b * NCHK + c) * 16 + tid) * 16;
#pragma unroll
        for (int q = 0; q < 4; q++)
            *(float4*)(dst + q * 4) =
                make_float4(o[4*q], o[4*q+1], o[4*q+2], o[4*q+3]);
        if (tid == 0) g_R[b * NCHK + c] = gmax;
    }
}

// ---------------------------------------------------------------------------
// Pair kernel: 32-step matrices, pure linear matmul.
// M32[c] = M[2c+1] o M[2c]:  C[j][i] = sum_k PB[j][k] * PA[k][i]
// ---------------------------------------------------------------------------
__global__ __launch_bounds__(256) void pair_kernel()
{
    const int c = blockIdx.x, b = blockIdx.y;
    const int tid = threadIdx.x;
    const int r = tid >> 4, q = tid & 15;

    __shared__ float As[16][17];
    __shared__ float Bs[16][17];
    __shared__ float Cs[16][17];
    __shared__ float rms[16];

    As[r][q] = g_P[(size_t)((b * NCHK + 2*c)     * 16 + r) * 16 + q];
    Bs[r][q] = g_P[(size_t)((b * NCHK + 2*c + 1) * 16 + r) * 16 + q];
    const float RA = g_R[b * NCHK + 2*c];
    const float RB = g_R[b * NCHK + 2*c + 1];
    __syncthreads();

    float s = 0.f;
#pragma unroll
    for (int k = 0; k < 16; k++)
        s = fmaf(Bs[r][k], As[k][q], s);
    Cs[r][q] = s;
    __syncthreads();

    if (tid < 16) {
        float rm = Cs[tid][0];
#pragma unroll
        for (int i = 1; i < 16; i++) rm = fmaxf(rm, Cs[tid][i]);
        rms[tid] = rm;
    }
    __syncthreads();
    if (tid < 16) {
        float gmax = rms[0];
#pragma unroll
        for (int i = 1; i < 16; i++) gmax = fmaxf(gmax, rms[i]);
        const float inv = __fdividef(1.f, gmax);
        float* dst = g_P32 + (size_t)((b * NP2 + c) * 16 + tid) * 16;
#pragma unroll
        for (int u = 0; u < 4; u++) {
            float4 v;
            v.x = Cs[tid][4*u]   * inv;
            v.y = Cs[tid][4*u+1] * inv;
            v.z = Cs[tid][4*u+2] * inv;
            v.w = Cs[tid][4*u+3] * inv;
            *(float4*)(dst + u * 4) = v;
        }
        if (tid == 0) g_R32[b * NP2 + c] = RA + RB + __logf(gmax);
    }
}

// ---------------------------------------------------------------------------
// Scan phase 2: linear-space combine, one exchange per iter, rolled loops.
// ---------------------------------------------------------------------------
__global__ __launch_bounds__(64) void scan_p2(
    const float* __restrict__ trans, const int* __restrict__ lens,
    const int* __restrict__ tags, float* __restrict__ out)
{
    const int b   = blockIdx.x;
    const int tid = threadIdx.x;
    const unsigned F = 0xffffffffu;
    const int len   = lens[b];
    const int last  = len - 1;
    const int nfull = last >> 4;       // 15..31
    const int nrem  = last & 15;
    const int nf32  = nfull >> 1;      // 7..15
    const int odd   = nfull & 1;

    __shared__ float sOut[2];
    __shared__ __align__(16) float sW[2][16];

    if (tid < 16) {
        const int jj = tid;
        // Texp
        float Trow[16];
#pragma unroll
        for (int i = 0; i < 16; i++) Trow[i] = trans[jj * KK_ + i];
        float maxT = Trow[0];
#pragma unroll
        for (int i = 1; i < 16; i++) maxT = fmaxf(maxT, Trow[i]);
#pragma unroll
        for (int off = 8; off; off >>= 1)
            maxT = fmaxf(maxT, __shfl_xor_sync(0xffffu, maxT, off, 16));
        float4 T0, T1, T2, T3;
        {
            float te[16];
#pragma unroll
            for (int i = 0; i < 16; i++) te[i] = __expf(Trow[i] - maxT);
            T0 = make_float4(te[0], te[1], te[2], te[3]);
            T1 = make_float4(te[4], te[5], te[6], te[7]);
            T2 = make_float4(te[8], te[9], te[10], te[11]);
            T3 = make_float4(te[12], te[13], te[14], te[15]);
        }

        // init from em[t=0]
        const float em00 = g_em[(size_t)b * KK_];
        float L = em00;
        sW[0][jj] = __expf(g_em[(size_t)b * KK_ + jj] - em00);
        __syncwarp(0xffffu);
        float4 t0 = *(const float4*)(sW[0] + 0);
        float4 t1 = *(const float4*)(sW[0] + 4);
        float4 t2 = *(const float4*)(sW[0] + 8);
        float4 t3 = *(const float4*)(sW[0] + 12);
        int pb = 1;

        // ---- 32-step combines ----
#pragma unroll 1
        for (int c = 0; c < nf32; c++) {
            const float* src = g_P32 + ((size_t)(b * NP2 + c) * 16 + jj) * 16;
            const float4 P0 = *(const float4*)(src);
            const float4 P1 = *(const float4*)(src + 4);
            const float4 P2 = *(const float4*)(src + 8);
            const float4 P3 = *(const float4*)(src + 12);
            const float  R  = g_R32[b * NP2 + c];
            const float w = dot16(t0, t1, t2, t3, P0, P1, P2, P3);
            sW[pb][jj] = w;
            __syncwarp(0xffffu);
            const float w0  = sW[pb][0];
            const float rcp = __fdividef(1.f, w0);
            L += R + __logf(w0);
            float4 u0 = *(const float4*)(sW[pb] + 0);
            float4 u1 = *(const float4*)(sW[pb] + 4);
            float4 u2 = *(const float4*)(sW[pb] + 8);
            float4 u3 = *(const float4*)(sW[pb] + 12);
            t0 = make_float4(u0.x*rcp, u0.y*rcp, u0.z*rcp, u0.w*rcp);
            t1 = make_float4(u1.x*rcp, u1.y*rcp, u1.z*rcp, u1.w*rcp);
            t2 = make_float4(u2.x*rcp, u2.y*rcp, u2.z*rcp, u2.w*rcp);
            t3 = make_float4(u3.x*rcp, u3.y*rcp, u3.z*rcp, u3.w*rcp);
            pb ^= 1;
        }

        // ---- odd 16-step chunk ----
        if (odd) {
            const int co = 2 * nf32;
            const float* src = g_P + ((size_t)(b * NCHK + co) * 16 + jj) * 16;
            const float4 P0 = *(const float4*)(src);
            const float4 P1 = *(const float4*)(src + 4);
            const float4 P2 = *(const float4*)(src + 8);
            const float4 P3 = *(const float4*)(src + 12);
            const float  R  = g_R[b * NCHK + co];
            const float w = dot16(t0, t1, t2, t3, P0, P1, P2, P3);
            sW[pb][jj] = w;
            __syncwarp(0xffffu);
            const float w0  = sW[pb][0];
            const float rcp = __fdividef(1.f, w0);
            L += R + __logf(w0);
            float4 u0 = *(const float4*)(sW[pb] + 0);
            float4 u1 = *(const float4*)(sW[pb] + 4);
            float4 u2 = *(const float4*)(sW[pb] + 8);
            float4 u3 = *(const float4*)(sW[pb] + 12);
            t0 = make_float4(u0.x*rcp, u0.y*rcp, u0.z*rcp, u0.w*rcp);
            t1 = make_float4(u1.x*rcp, u1.y*rcp, u1.z*rcp, u1.w*rcp);
            t2 = make_float4(u2.x*rcp, u2.y*rcp, u2.z*rcp, u2.w*rcp);
            t3 = make_float4(u3.x*rcp, u3.y*rcp, u3.z*rcp, u3.w*rcp);
            pb ^= 1;
        }

        // ---- elementary remainder steps ----
#pragma unroll 1
        for (int s = 0; s < nrem; s++) {
            const int tt = 16 * nfull + 1 + s;
            const float em0 = g_em[(size_t)(tt * B_ + b) * KK_];
            const float esc = __expf(g_em[(size_t)(tt * B_ + b) * KK_ + jj] - em0);
            const float w = dot16(t0, t1, t2, t3, T0, T1, T2, T3) * esc;
            sW[pb][jj] = w;
            __syncwarp(0xffffu);
            const float w0  = sW[pb][0];
            const float rcp = __fdividef(1.f, w0);
            L += maxT + em0 + __logf(w0);
            float4 u0 = *(const float4*)(sW[pb] + 0);
            float4 u1 = *(const float4*)(sW[pb] + 4);
            float4 u2 = *(const float4*)(sW[pb] + 8);
            float4 u3 = *(const float4*)(sW[pb] + 12);
            t0 = make_float4(u0.x*rcp, u0.y*rcp, u0.z*rcp, u0.w*rcp);
            t1 = make_float4(u1.x*rcp, u1.y*rcp, u1.z*rcp, u1.w*rcp);
            t2 = make_float4(u2.x*rcp, u2.y*rcp, u2.z*rcp, u2.w*rcp);
            t3 = make_float4(u3.x*rcp, u3.y*rcp, u3.z*rcp, u3.w*rcp);
            pb ^= 1;
        }

        // final: fwd = L + log(sum_i t_i)
        if (jj == 0) {
            float s = (t0.x + t0.y + t0.z + t0.w)
                    + (t1.x + t1.y + t1.z + t1.w)
                    + (t2.x + t2.y + t2.z + t2.w)
                    + (t3.x + t3.y + t3.z + t3.w);
            sOut[0] = L + __logf(s);
        }
    } else if (tid >= 32) {
        const int lane = tid - 32;
        float g = 0.f;
#pragma unroll
        for (int t = 0; t < 16; t++) {
            const int tt = lane + t * 32;
            if (tt < len) {
                const int tag = tags[tt * B_ + b];
                float v = g_em[(size_t)(tt * B_ + b) * KK_ + tag];
                if (tt > 0) {
                    const int tp = tags[(tt - 1) * B_ + b];
                    v += trans[tag * KK_ + tp];
                }
                g += v;
            }
        }
#pragma unroll
        for (int off = 16; off; off >>= 1)
            g += __shfl_xor_sync(F, g, off);
        if (lane == 0) sOut[1] = g;
    }
    __syncthreads();
    if (tid == 0) atomicAdd(out, sOut[0] - sOut[1]);
}

// ---------------------------------------------------------------------------
extern "C" void kernel_launch(void* const* d_in, const int* in_sizes, int n_in,
                              void* d_out, int out_size)
{
    (void)in_sizes; (void)n_in; (void)out_size;
    const float* hidden = (const float*)d_in[0];
    const float* W1     = (const float*)d_in[1];
    const float* b1     = (const float*)d_in[2];
    const float* W2     = (const float*)d_in[3];
    const float* b2     = (const float*)d_in[4];
    const float* trans  = (const float*)d_in[5];
    const int*   lens   = (const int*)d_in[6];
    const int*   tags   = (const int*)d_in[7];

    cudaFuncSetAttribute(gemm1_fused, cudaFuncAttributeMaxDynamicSharedMemorySize,
                         SMEM_BYTES);

    prep_kernel<<<PREP_TOTAL, 256>>>(hidden, W1, b2, (float*)d_out);
    gemm1_fused<<<dim3(H_ / BN, M_ / BM), 256, SMEM_BYTES>>>(b1, W2);
    scan_p1<<<dim3(NCHK, B_), 256>>>(trans);
    pair_kernel<<<dim3(NP2, B_), 256>>>();
    scan_p2<<<B_, 64>>>(trans, lens, tags, (float*)d_out);
}